// round 14
// baseline (speedup 1.0000x reference)
#include <cuda_runtime.h>
#include <cuda_bf16.h>
#include <math.h>
#include <stdint.h>

// Problem constants
#define NN 13
#define BB 2
#define TT 2048
#define DD 1024
#define ROW_F4 (DD / 4)          // 256 float4 per row
#define NTILES (BB * TT)         // 4096
#define CWARPS 16                // compute warps
#define CTHREADS 512             // compute threads
#define THREADS 544              // + 1 producer warp
#define GRID 152                 // 1 CTA per SM
#define SLOTS 3
#define EPS 1.1920928955078125e-07f   // FLT_EPSILON

#define BUF_F4      (NN * ROW_F4)
#define TILE_BYTES  (BUF_F4 * 16)            // 53248
#define SMEM_BYTES  (SLOTS * TILE_BYTES)     // 159744

__device__ __forceinline__ uint32_t smem_u32(const void* p) {
    uint32_t a;
    asm("{ .reg .u64 t; cvta.to.shared.u64 t, %1; cvt.u32.u64 %0, t; }"
        : "=r"(a) : "l"(p));
    return a;
}
__device__ __forceinline__ void mbar_init(uint32_t m, uint32_t cnt) {
    asm volatile("mbarrier.init.shared.b64 [%0], %1;" :: "r"(m), "r"(cnt) : "memory");
}
__device__ __forceinline__ void mbar_expect_tx(uint32_t m, uint32_t bytes) {
    asm volatile("mbarrier.arrive.expect_tx.shared.b64 _, [%0], %1;"
                 :: "r"(m), "r"(bytes) : "memory");
}
__device__ __forceinline__ void mbar_arrive(uint32_t m) {
    asm volatile("mbarrier.arrive.shared.b64 _, [%0];" :: "r"(m) : "memory");
}
__device__ __forceinline__ void mbar_wait(uint32_t m, uint32_t parity) {
    asm volatile(
        "{\n\t.reg .pred P;\n\t"
        "WAIT_%=:\n\t"
        "mbarrier.try_wait.parity.acquire.cta.shared::cta.b64 P, [%0], %1, 0x989680;\n\t"
        "@P bra DONE_%=;\n\t"
        "bra WAIT_%=;\n\t"
        "DONE_%=:\n\t}"
        :: "r"(m), "r"(parity) : "memory");
}
__device__ __forceinline__ void tma_1d(uint32_t dst, const void* src,
                                       uint32_t bytes, uint32_t mbar) {
    asm volatile(
        "cp.async.bulk.shared::cta.global.mbarrier::complete_tx::bytes [%0], [%1], %2, [%3];"
        :: "r"(dst), "l"(src), "r"(bytes), "r"(mbar) : "memory");
}

__global__ __launch_bounds__(THREADS, 1)
void attn_res_block_kernel(const float4* __restrict__ V,
                           const float4* __restrict__ rms_w,
                           const float4* __restrict__ w_proj,
                           float4* __restrict__ out)
{
    extern __shared__ float4 sbuf[];                  // [SLOTS][NN][ROW_F4]
    __shared__ __align__(8) uint64_t mb_full[SLOTS];  // tx-count completion
    __shared__ __align__(8) uint64_t mb_empty[SLOTS]; // 16 consumer arrivals
    __shared__ float s_logit[SLOTS][NN];

    const int tid  = threadIdx.x;
    const int lane = tid & 31;
    const int wid  = tid >> 5;                        // 0..16

    const uint32_t full_a  = smem_u32(&mb_full[0]);
    const uint32_t empty_a = smem_u32(&mb_empty[0]);
    const uint32_t sb_a    = smem_u32(sbuf);

    if (tid == 0) {
        #pragma unroll
        for (int s = 0; s < SLOTS; s++) {
            mbar_init(full_a  + s * 8, 1);
            mbar_init(empty_a + s * 8, CWARPS);
        }
        asm volatile("fence.proxy.async.shared::cta;" ::: "memory");
    }
    __syncthreads();

    // ================= Producer warp (wid == 16) =================
    if (wid == CWARPS) {
        if (lane == 0) {
            int pe0 = 0, pe1 = 0, pe2 = 0;
            int s = 0, j = 0;
            for (int t = blockIdx.x; t < NTILES; t += GRID, j++) {
                if (j >= SLOTS) {                     // wait for slot consumed
                    if      (s == 0) { mbar_wait(empty_a,      pe0); pe0 ^= 1; }
                    else if (s == 1) { mbar_wait(empty_a + 8,  pe1); pe1 ^= 1; }
                    else             { mbar_wait(empty_a + 16, pe2); pe2 ^= 1; }
                }
                mbar_expect_tx(full_a + s * 8, TILE_BYTES);
                #pragma unroll
                for (int n = 0; n < NN; n++)
                    tma_1d(sb_a + (uint32_t)(s * BUF_F4 + n * ROW_F4) * 16u,
                           (const void*)(V + ((long)n * NTILES + t) * ROW_F4),
                           (uint32_t)(ROW_F4 * 16), full_a + s * 8);
                s = (s == SLOTS - 1) ? 0 : s + 1;
            }
        }
        return;
    }

    // ================= Consumer warps (tid < 512) =================
    // Lane-indexed combined weight (rms_weight * w_proj), registers.
    // Phase-1 row view: lane covers float4 columns k*32+lane.
    float4 cw[8];
    #pragma unroll
    for (int k = 0; k < 8; k++) {
        float4 a = rms_w[k * 32 + lane];
        float4 b = w_proj[k * 32 + lane];
        cw[k] = make_float4(a.x * b.x, a.y * b.y, a.z * b.z, a.w * b.w);
    }

    int pf0 = 0, pf1 = 0, pf2 = 0;
    int s = 0;
    for (int tile = blockIdx.x; tile < NTILES; tile += GRID) {
        if      (s == 0) { mbar_wait(full_a,      pf0); pf0 ^= 1; }
        else if (s == 1) { mbar_wait(full_a + 8,  pf1); pf1 ^= 1; }
        else             { mbar_wait(full_a + 16, pf2); pf2 ^= 1; }

        const float4* cur = sbuf + s * BUF_F4;

        // ---- Phase 1 (row-mapped): warp w owns row w (w < 13).
        if (wid < NN) {
            float tss = 0.f, tdp = 0.f;
            #pragma unroll
            for (int k = 0; k < 8; k++) {
                float4 x = cur[wid * ROW_F4 + k * 32 + lane];
                tss = fmaf(x.x, x.x, fmaf(x.y, x.y, fmaf(x.z, x.z, fmaf(x.w, x.w, tss))));
                tdp = fmaf(x.x, cw[k].x, fmaf(x.y, cw[k].y, fmaf(x.z, cw[k].z, fmaf(x.w, cw[k].w, tdp))));
            }
            #pragma unroll
            for (int off = 16; off > 0; off >>= 1) {
                tss += __shfl_xor_sync(0xFFFFFFFFu, tss, off);
                tdp += __shfl_xor_sync(0xFFFFFFFFu, tdp, off);
            }
            if (lane == 0)
                s_logit[s][wid] = rsqrtf(tss * (1.0f / DD) + EPS) * tdp;
        }
        // B1: compute warps only (named barrier; producer excluded).
        asm volatile("bar.sync 1, %0;" :: "n"(CTHREADS) : "memory");

        // ---- Softmax: per-warp redundant; values in lanes 0..12 -> 4 steps.
        float lv = (lane < NN) ? s_logit[s][lane] : -INFINITY;
        float mx = lv;
        #pragma unroll
        for (int off = 8; off > 0; off >>= 1)
            mx = fmaxf(mx, __shfl_xor_sync(0xFFFFFFFFu, mx, off));
        float e = (lane < NN) ? __expf(lv - mx) : 0.f;
        float sm = e;
        #pragma unroll
        for (int off = 8; off > 0; off >>= 1)
            sm += __shfl_xor_sync(0xFFFFFFFFu, sm, off);
        const float av = e * (1.0f / sm);          // alpha for depth = lane

        // ---- Phase 2 (column-mapped, float2 per thread over 512 threads).
        {
            const float2* cur2 = reinterpret_cast<const float2*>(cur);
            float2 o = make_float2(0.f, 0.f);
            #pragma unroll
            for (int n = 0; n < NN; n++) {
                float2 x = cur2[n * 512 + tid];
                float an = __shfl_sync(0xFFFFFFFFu, av, n);
                o.x = fmaf(an, x.x, o.x);
                o.y = fmaf(an, x.y, o.y);
            }
            reinterpret_cast<float2*>(out)[(long)tile * 512 + tid] = o;
        }

        // Slot consumed by this warp (convergent) -> non-blocking arrive.
        if (lane == 0) mbar_arrive(empty_a + s * 8);

        s = (s == SLOTS - 1) ? 0 : s + 1;
    }
}

extern "C" void kernel_launch(void* const* d_in, const int* in_sizes, int n_in,
                              void* d_out, int out_size)
{
    const float4* V      = (const float4*)d_in[0];   // [13,2,2048,1024] f32
    const float4* rms_w  = (const float4*)d_in[1];   // [1024] f32
    const float4* w_proj = (const float4*)d_in[2];   // [1024] f32
    float4* out          = (float4*)d_out;           // [2,2048,1024] f32

    cudaFuncSetAttribute(attn_res_block_kernel,
                         cudaFuncAttributeMaxDynamicSharedMemorySize, SMEM_BYTES);

    attn_res_block_kernel<<<GRID, THREADS, SMEM_BYTES>>>(V, rms_w, w_proj, out);
}